// round 1
// baseline (speedup 1.0000x reference)
#include <cuda_runtime.h>
#include <math.h>

// Problem constants
#define BATCH  2
#define SEQ    2048
#define DMODEL 4096
#define NH     32
#define NKV    8
#define HDIM   128
#define MTOT   (BATCH*SEQ)      // 4096 rows

// Flash-attention tiling
#define BQ 64
#define BK 64
#define QSTR 68                  // padded row stride (floats), 16B-aligned rows
#define KSTR 68
#define PSTR 68

// -------- scratch (device globals: no allocation allowed) --------
__device__ float g_q [(size_t)BATCH*SEQ*NH *HDIM];   // 16.8M floats
__device__ float g_k [(size_t)BATCH*SEQ*NKV*HDIM];   //  4.2M
__device__ float g_v [(size_t)BATCH*SEQ*NKV*HDIM];   //  4.2M
__device__ float g_ao[(size_t)BATCH*SEQ*NH *HDIM];   // 16.8M

// =====================================================================
// GEMM: C[M,N] = A[M,K] @ W[K,N] (+ bias). 128x128x8 tile, 256 threads,
// 8x8 micro-tile per thread, register prefetch of next k-slab.
// M,N,K all multiples of 128/8 here, so no edge handling.
// =====================================================================
__global__ void __launch_bounds__(256) gemm_kernel(
    const float* __restrict__ A, const float* __restrict__ W,
    const float* __restrict__ bias, float* __restrict__ C,
    int M, int N, int K)
{
    __shared__ float As[8][128];   // transposed: As[k][m]
    __shared__ float Bs[8][128];   // Bs[k][n]

    const int tid = threadIdx.x;
    const int tx  = tid & 15;       // n-group
    const int ty  = tid >> 4;       // m-group
    const int m0  = blockIdx.y * 128;
    const int n0  = blockIdx.x * 128;

    const int am  = tid >> 1;            // A row within tile (0..127)
    const int ak4 = (tid & 1) * 4;       // A k offset {0,4}
    const int bk  = tid >> 5;            // B k row (0..7)
    const int bn4 = (tid & 31) * 4;      // B n offset

    const float* Aptr = A + (size_t)(m0 + am) * K + ak4;
    const float* Wptr = W + (size_t)bk * N + n0 + bn4;

    float4 av = *(const float4*)Aptr;
    float4 bv = *(const float4*)Wptr;

    float acc[8][8];
    #pragma unroll
    for (int i = 0; i < 8; i++)
        #pragma unroll
        for (int j = 0; j < 8; j++) acc[i][j] = 0.f;

    for (int kt = 0; kt < K; kt += 8) {
        As[ak4+0][am] = av.x; As[ak4+1][am] = av.y;
        As[ak4+2][am] = av.z; As[ak4+3][am] = av.w;
        *(float4*)&Bs[bk][bn4] = bv;
        __syncthreads();

        if (kt + 8 < K) {
            av = *(const float4*)(Aptr + kt + 8);
            bv = *(const float4*)(Wptr + (size_t)(kt + 8) * N);
        }

        #pragma unroll
        for (int kk = 0; kk < 8; kk++) {
            float4 a0 = *(const float4*)&As[kk][ty*8];
            float4 a1 = *(const float4*)&As[kk][ty*8+4];
            float4 b0 = *(const float4*)&Bs[kk][tx*8];
            float4 b1 = *(const float4*)&Bs[kk][tx*8+4];
            float a[8] = {a0.x,a0.y,a0.z,a0.w,a1.x,a1.y,a1.z,a1.w};
            float b[8] = {b0.x,b0.y,b0.z,b0.w,b1.x,b1.y,b1.z,b1.w};
            #pragma unroll
            for (int i = 0; i < 8; i++)
                #pragma unroll
                for (int j = 0; j < 8; j++)
                    acc[i][j] += a[i]*b[j];
        }
        __syncthreads();
    }

    float bs[8];
    #pragma unroll
    for (int j = 0; j < 8; j++)
        bs[j] = bias ? bias[n0 + tx*8 + j] : 0.f;

    #pragma unroll
    for (int i = 0; i < 8; i++) {
        int row = m0 + ty*8 + i;
        float* cp = C + (size_t)row * N + n0 + tx*8;
        float4 o0 = make_float4(acc[i][0]+bs[0], acc[i][1]+bs[1],
                                acc[i][2]+bs[2], acc[i][3]+bs[3]);
        float4 o1 = make_float4(acc[i][4]+bs[4], acc[i][5]+bs[5],
                                acc[i][6]+bs[6], acc[i][7]+bs[7]);
        *(float4*)cp       = o0;
        *(float4*)(cp + 4) = o1;
    }
}

// =====================================================================
// RoPE (in-place). One thread per (row, j) pair, j in [0,64).
// Angle computed in double, range-reduced, then float sincos.
// =====================================================================
__global__ void rope_kernel(float* __restrict__ x, const int* __restrict__ pos_ids,
                            int nh, int total)
{
    int idx = blockIdx.x * blockDim.x + threadIdx.x;
    if (idx >= total) return;
    int j   = idx & 63;
    int row = idx >> 6;                 // (b*SEQ + s)*nh + h
    int bs  = row / nh;                 // b*SEQ + s
    int pos = pos_ids[bs];

    // freq = theta^(-j/64), theta = 1e6 ; log2(1e6)/64 = 0.31143075889569021
    double freq = exp2(-(double)j * 0.31143075889569021);
    double ang  = (double)pos * freq;
    double kq   = rint(ang * 0.15915494309189533577);       // /(2*pi)
    float  a    = (float)(ang - kq * 6.28318530717958647693);
    float  c, sn;
    __sincosf(a, &sn, &c);

    float* p = x + (size_t)row * HDIM + j;
    float x1 = p[0], x2 = p[64];
    p[0]  = x1*c  - x2*sn;
    p[64] = x1*sn + x2*c;
}

// =====================================================================
// Flash attention (causal, GQA rep=4), fp32.
// Block: 64 q-rows x one head x one batch, 256 threads (16x16).
// smem: Qt[HD][68] (transposed, pre-scaled), Kt[HD][68] (transposed),
//       Vs[64][128], Pt[64][68] (transposed probs).
// =====================================================================
__global__ void __launch_bounds__(256) flash_kernel(
    const float* __restrict__ qg, const float* __restrict__ kg,
    const float* __restrict__ vg, float* __restrict__ ao)
{
    extern __shared__ float smem[];
    float* Qt = smem;                       // HDIM * QSTR
    float* Kt = Qt + HDIM * QSTR;           // HDIM * KSTR
    float* Vs = Kt + HDIM * KSTR;           // BK * HDIM
    float* Pt = Vs + BK * HDIM;             // BK * PSTR

    const int tid = threadIdx.x;
    const int tx  = tid & 15;
    const int ty  = tid >> 4;
    const int qt0 = blockIdx.x * BQ;
    const int h   = blockIdx.y;
    const int b   = blockIdx.z;
    const int kvh = h >> 2;                 // NREP = 4
    const float scale = 0.08838834764831843f;  // 1/sqrt(128)

    // Load + transpose + pre-scale Q tile
    for (int idx = tid; idx < 32*BQ; idx += 256) {
        int i  = idx & (BQ-1);
        int d4 = (idx >> 6) << 2;
        float4 val = *(const float4*)(qg + (((size_t)(b*SEQ + qt0 + i)*NH + h) << 7) + d4);
        Qt[(d4+0)*QSTR + i] = val.x * scale;
        Qt[(d4+1)*QSTR + i] = val.y * scale;
        Qt[(d4+2)*QSTR + i] = val.z * scale;
        Qt[(d4+3)*QSTR + i] = val.w * scale;
    }

    float m[4], l[4], acc[4][8];
    #pragma unroll
    for (int i = 0; i < 4; i++) {
        m[i] = -1e30f; l[i] = 0.f;
        #pragma unroll
        for (int j = 0; j < 8; j++) acc[i][j] = 0.f;
    }

    const int ntiles = qt0 / BK + 1;
    for (int kt = 0; kt < ntiles; kt++) {
        const int kt0 = kt * BK;

        // Load K (transposed) and V (row-major)
        for (int idx = tid; idx < 32*BK; idx += 256) {
            int j  = idx & (BK-1);
            int d4 = (idx >> 6) << 2;
            float4 kk = *(const float4*)(kg + (((size_t)((b*SEQ + kt0 + j)*NKV) + kvh) << 7) + d4);
            Kt[(d4+0)*KSTR + j] = kk.x;
            Kt[(d4+1)*KSTR + j] = kk.y;
            Kt[(d4+2)*KSTR + j] = kk.z;
            Kt[(d4+3)*KSTR + j] = kk.w;
        }
        for (int idx = tid; idx < 32*BK; idx += 256) {
            int j  = idx >> 5;
            int d4 = (idx & 31) << 2;
            *(float4*)&Vs[j*HDIM + d4] =
                *(const float4*)(vg + (((size_t)((b*SEQ + kt0 + j)*NKV) + kvh) << 7) + d4);
        }
        __syncthreads();

        // Scores s[i][j] over 4x4 micro-tile
        float s[4][4];
        #pragma unroll
        for (int i = 0; i < 4; i++)
            #pragma unroll
            for (int j = 0; j < 4; j++) s[i][j] = 0.f;

        #pragma unroll 8
        for (int d = 0; d < HDIM; d++) {
            float4 aq = *(const float4*)&Qt[d*QSTR + ty*4];
            float4 bk4 = *(const float4*)&Kt[d*KSTR + tx*4];
            float a[4] = {aq.x, aq.y, aq.z, aq.w};
            float bb[4] = {bk4.x, bk4.y, bk4.z, bk4.w};
            #pragma unroll
            for (int i = 0; i < 4; i++)
                #pragma unroll
                for (int j = 0; j < 4; j++)
                    s[i][j] += a[i]*bb[j];
        }

        // Causal mask (only possible on last tile: kt0 == qt0)
        if (kt == ntiles - 1) {
            #pragma unroll
            for (int ii = 0; ii < 4; ii++)
                #pragma unroll
                for (int jj = 0; jj < 4; jj++)
                    if (kt0 + tx*4 + jj > qt0 + ty*4 + ii) s[ii][jj] = -1e30f;
        }

        // Online softmax (row-wise across 16 tx threads)
        #pragma unroll
        for (int ii = 0; ii < 4; ii++) {
            float tm = fmaxf(fmaxf(s[ii][0], s[ii][1]), fmaxf(s[ii][2], s[ii][3]));
            #pragma unroll
            for (int o = 8; o > 0; o >>= 1)
                tm = fmaxf(tm, __shfl_xor_sync(0xffffffffu, tm, o, 16));
            float mn = fmaxf(m[ii], tm);
            float al = __expf(m[ii] - mn);
            float rs = 0.f;
            #pragma unroll
            for (int jj = 0; jj < 4; jj++) {
                float p = __expf(s[ii][jj] - mn);
                s[ii][jj] = p;
                rs += p;
            }
            #pragma unroll
            for (int o = 8; o > 0; o >>= 1)
                rs += __shfl_xor_sync(0xffffffffu, rs, o, 16);
            l[ii] = l[ii]*al + rs;
            m[ii] = mn;
            #pragma unroll
            for (int jj = 0; jj < 8; jj++) acc[ii][jj] *= al;
        }

        // Write P transposed: Pt[key][qrow]
        #pragma unroll
        for (int jj = 0; jj < 4; jj++) {
            float4 pv = make_float4(s[0][jj], s[1][jj], s[2][jj], s[3][jj]);
            *(float4*)&Pt[(tx*4 + jj)*PSTR + ty*4] = pv;
        }
        __syncthreads();

        // O += P @ V  (thread owns rows ty*4..+3, cols tx*8..+7)
        #pragma unroll 4
        for (int j = 0; j < BK; j++) {
            float4 pa = *(const float4*)&Pt[j*PSTR + ty*4];
            float4 v0 = *(const float4*)&Vs[j*HDIM + tx*8];
            float4 v1 = *(const float4*)&Vs[j*HDIM + tx*8 + 4];
            float pr[4] = {pa.x, pa.y, pa.z, pa.w};
            #pragma unroll
            for (int ii = 0; ii < 4; ii++) {
                acc[ii][0] += pr[ii]*v0.x; acc[ii][1] += pr[ii]*v0.y;
                acc[ii][2] += pr[ii]*v0.z; acc[ii][3] += pr[ii]*v0.w;
                acc[ii][4] += pr[ii]*v1.x; acc[ii][5] += pr[ii]*v1.y;
                acc[ii][6] += pr[ii]*v1.z; acc[ii][7] += pr[ii]*v1.w;
            }
        }
        __syncthreads();
    }

    // Normalize and write attention output [b][s][h][d]
    #pragma unroll
    for (int ii = 0; ii < 4; ii++) {
        float inv = 1.f / l[ii];
        int qi = qt0 + ty*4 + ii;
        float* dst = ao + (((size_t)(b*SEQ + qi)*NH + h) << 7) + tx*8;
        float4 o0 = make_float4(acc[ii][0]*inv, acc[ii][1]*inv,
                                acc[ii][2]*inv, acc[ii][3]*inv);
        float4 o1 = make_float4(acc[ii][4]*inv, acc[ii][5]*inv,
                                acc[ii][6]*inv, acc[ii][7]*inv);
        *(float4*)dst       = o0;
        *(float4*)(dst + 4) = o1;
    }
}

// =====================================================================
// Launch
// =====================================================================
extern "C" void kernel_launch(void* const* d_in, const int* in_sizes, int n_in,
                              void* d_out, int out_size)
{
    const float* hidden = (const float*)d_in[0];
    const int*   pos    = (const int*)  d_in[1];
    const float* wq     = (const float*)d_in[2];
    const float* bq     = (const float*)d_in[3];
    const float* wk     = (const float*)d_in[4];
    const float* bk     = (const float*)d_in[5];
    const float* wv     = (const float*)d_in[6];
    const float* bv     = (const float*)d_in[7];
    const float* wo     = (const float*)d_in[8];
    float* out = (float*)d_out;

    float *qp, *kp, *vp, *aop;
    cudaGetSymbolAddress((void**)&qp,  g_q);
    cudaGetSymbolAddress((void**)&kp,  g_k);
    cudaGetSymbolAddress((void**)&vp,  g_v);
    cudaGetSymbolAddress((void**)&aop, g_ao);

    // QKV projections
    gemm_kernel<<<dim3((NH *HDIM)/128, MTOT/128), 256>>>(hidden, wq, bq, qp, MTOT, NH *HDIM, DMODEL);
    gemm_kernel<<<dim3((NKV*HDIM)/128, MTOT/128), 256>>>(hidden, wk, bk, kp, MTOT, NKV*HDIM, DMODEL);
    gemm_kernel<<<dim3((NKV*HDIM)/128, MTOT/128), 256>>>(hidden, wv, bv, vp, MTOT, NKV*HDIM, DMODEL);

    // RoPE on q and k
    int tq = BATCH*SEQ*NH *64;
    int tk = BATCH*SEQ*NKV*64;
    rope_kernel<<<(tq + 255)/256, 256>>>(qp, pos, NH,  tq);
    rope_kernel<<<(tk + 255)/256, 256>>>(kp, pos, NKV, tk);

    // Flash attention
    size_t smbytes = (size_t)(HDIM*QSTR + HDIM*KSTR + BK*HDIM + BK*PSTR) * sizeof(float);
    cudaFuncSetAttribute(flash_kernel, cudaFuncAttributeMaxDynamicSharedMemorySize, (int)smbytes);
    flash_kernel<<<dim3(SEQ/BQ, NH, BATCH), 256, smbytes>>>(qp, kp, vp, aop);

    // Output projection (no bias)
    gemm_kernel<<<dim3(DMODEL/128, MTOT/128), 256>>>(aop, wo, nullptr, out, MTOT, DMODEL, DMODEL);
}

// round 3
// speedup vs baseline: 1.8630x; 1.8630x over previous
#include <cuda_runtime.h>
#include <cuda_bf16.h>
#include <cstdint>
#include <math.h>

// Problem constants
#define BATCH  2
#define SEQ    2048
#define DMODEL 4096
#define NH     32
#define NKV    8
#define HDIM   128
#define MTOT   (BATCH*SEQ)        // 4096 rows
#define QKVN   6144               // 4096 q + 1024 k + 1024 v

// Flash-attention tiling
#define BQ 64
#define BK 64
#define QSTR 68
#define KSTR 68
#define PSTR 68

// mma.sync GEMM tiling
#define GMT 128
#define GNT 128
#define GKC 32
#define GSTAGES 3
#define OP_BYTES  (128*GKC*2)          // one operand tile: 8KB
#define STG_BYTES (4*OP_BYTES)         // Ahi,Alo,Bhi,Blo: 32KB
#define GEMM_SMEM (GSTAGES*STG_BYTES)  // 96KB

// -------- scratch (device globals: no allocation allowed) --------
__device__ __align__(16) __nv_bfloat16 g_hid_hi [(size_t)MTOT*DMODEL];
__device__ __align__(16) __nv_bfloat16 g_hid_lo [(size_t)MTOT*DMODEL];
__device__ __align__(16) __nv_bfloat16 g_wqkv_hi[(size_t)QKVN*DMODEL];   // [n][k]
__device__ __align__(16) __nv_bfloat16 g_wqkv_lo[(size_t)QKVN*DMODEL];
__device__ __align__(16) __nv_bfloat16 g_wo_hi  [(size_t)DMODEL*DMODEL]; // [n][k]
__device__ __align__(16) __nv_bfloat16 g_wo_lo  [(size_t)DMODEL*DMODEL];
__device__ __align__(16) float g_qkv [(size_t)MTOT*QKVN];
__device__ __align__(16) float g_ao  [(size_t)MTOT*DMODEL];
__device__ __align__(16) __nv_bfloat16 g_ao_hi [(size_t)MTOT*DMODEL];
__device__ __align__(16) __nv_bfloat16 g_ao_lo [(size_t)MTOT*DMODEL];
__device__ float g_bias[QKVN];
__device__ float g_cos[SEQ*64];
__device__ float g_sin[SEQ*64];

// ======================= helpers =======================
__device__ __forceinline__ uint32_t smem_u32(const void* p) {
    uint32_t a;
    asm("{ .reg .u64 t; cvta.to.shared.u64 t, %1; cvt.u32.u64 %0, t; }" : "=r"(a) : "l"(p));
    return a;
}
__device__ __forceinline__ void cp16(uint32_t s, const void* g) {
    asm volatile("cp.async.cg.shared.global [%0], [%1], 16;" :: "r"(s), "l"(g));
}
#define CP_COMMIT()  asm volatile("cp.async.commit_group;" ::: "memory")
#define CP_WAIT(n)   asm volatile("cp.async.wait_group %0;" :: "n"(n) : "memory")

__device__ __forceinline__ void ldsm4(uint32_t& r0, uint32_t& r1, uint32_t& r2, uint32_t& r3,
                                      uint32_t a) {
    asm volatile("ldmatrix.sync.aligned.m8n8.x4.shared.b16 {%0,%1,%2,%3}, [%4];"
        : "=r"(r0), "=r"(r1), "=r"(r2), "=r"(r3) : "r"(a));
}
__device__ __forceinline__ void mma_bf16(float* c, const uint32_t* a, const uint32_t* b) {
    asm volatile("mma.sync.aligned.m16n8k16.row.col.f32.bf16.bf16.f32 "
        "{%0,%1,%2,%3}, {%4,%5,%6,%7}, {%8,%9}, {%0,%1,%2,%3};"
        : "+f"(c[0]), "+f"(c[1]), "+f"(c[2]), "+f"(c[3])
        : "r"(a[0]), "r"(a[1]), "r"(a[2]), "r"(a[3]), "r"(b[0]), "r"(b[1]));
}
__device__ __forceinline__ void split2(float x, unsigned short& h, unsigned short& l) {
    __nv_bfloat16 hb = __float2bfloat16(x);
    float hf = __bfloat162float(hb);
    __nv_bfloat16 lb = __float2bfloat16(x - hf);
    h = __bfloat16_as_ushort(hb);
    l = __bfloat16_as_ushort(lb);
}
// smem tile addressing: row r (0..127), 16B chunk c (0..3), XOR swizzle.
__device__ __forceinline__ uint32_t tile_off(int r, int c) {
    return (uint32_t)(r * 64 + ((c ^ ((r >> 1) & 3)) << 4));
}

// ======================= conversion kernels =======================
__global__ void conv_split_kernel(const float4* __restrict__ src,
                                  uint2* __restrict__ hi, uint2* __restrict__ lo, int n4)
{
    int i = blockIdx.x * blockDim.x + threadIdx.x;
    if (i >= n4) return;
    float4 v = src[i];
    float xs[4] = {v.x, v.y, v.z, v.w};
    unsigned short hs[4], ls[4];
    #pragma unroll
    for (int j = 0; j < 4; j++) split2(xs[j], hs[j], ls[j]);
    hi[i] = make_uint2((uint32_t)hs[0] | ((uint32_t)hs[1] << 16),
                       (uint32_t)hs[2] | ((uint32_t)hs[3] << 16));
    lo[i] = make_uint2((uint32_t)ls[0] | ((uint32_t)ls[1] << 16),
                       (uint32_t)ls[2] | ((uint32_t)ls[3] << 16));
}

// transpose-convert: B[n][k] = w[k][n], split into hi/lo
__global__ void conv_wqkv_kernel(const float* __restrict__ wq, const float* __restrict__ wk,
                                 const float* __restrict__ wv,
                                 __nv_bfloat16* __restrict__ bhi, __nv_bfloat16* __restrict__ blo)
{
    __shared__ float t[32][33];
    int k0 = blockIdx.x * 32, n0 = blockIdx.y * 32;
    int tx = threadIdx.x, ty = threadIdx.y;
    const float* src; int ld, nl;
    if (n0 < 4096)       { src = wq; ld = 4096; nl = n0; }
    else if (n0 < 5120)  { src = wk; ld = 1024; nl = n0 - 4096; }
    else                 { src = wv; ld = 1024; nl = n0 - 5120; }
    #pragma unroll
    for (int r = 0; r < 4; r++)
        t[ty + 8*r][tx] = src[(size_t)(k0 + ty + 8*r) * ld + nl + tx];
    __syncthreads();
    #pragma unroll
    for (int r = 0; r < 4; r++) {
        float x = t[tx][ty + 8*r];
        unsigned short h, l; split2(x, h, l);
        size_t o = (size_t)(n0 + ty + 8*r) * DMODEL + k0 + tx;
        bhi[o] = __ushort_as_bfloat16(h);
        blo[o] = __ushort_as_bfloat16(l);
    }
}

__global__ void conv_wo_kernel(const float* __restrict__ w,
                               __nv_bfloat16* __restrict__ bhi, __nv_bfloat16* __restrict__ blo)
{
    __shared__ float t[32][33];
    int k0 = blockIdx.x * 32, n0 = blockIdx.y * 32;
    int tx = threadIdx.x, ty = threadIdx.y;
    #pragma unroll
    for (int r = 0; r < 4; r++)
        t[ty + 8*r][tx] = w[(size_t)(k0 + ty + 8*r) * DMODEL + n0 + tx];
    __syncthreads();
    #pragma unroll
    for (int r = 0; r < 4; r++) {
        float x = t[tx][ty + 8*r];
        unsigned short h, l; split2(x, h, l);
        size_t o = (size_t)(n0 + ty + 8*r) * DMODEL + k0 + tx;
        bhi[o] = __ushort_as_bfloat16(h);
        blo[o] = __ushort_as_bfloat16(l);
    }
}

__global__ void concat_bias_kernel(const float* bq, const float* bk, const float* bv, float* out)
{
    int i = blockIdx.x * blockDim.x + threadIdx.x;
    if (i >= QKVN) return;
    out[i] = i < 4096 ? bq[i] : (i < 5120 ? bk[i - 4096] : bv[i - 5120]);
}

// ======================= RoPE =======================
__global__ void rope_table_kernel(float* __restrict__ ct, float* __restrict__ st)
{
    int idx = blockIdx.x * blockDim.x + threadIdx.x;
    if (idx >= SEQ * 64) return;
    int j = idx & 63, p = idx >> 6;
    double freq = exp2(-(double)j * 0.31143075889569021);
    double ang  = (double)p * freq;
    double kq   = rint(ang * 0.15915494309189533577);
    float  a    = (float)(ang - kq * 6.28318530717958647693);
    float c, s;
    __sincosf(a, &s, &c);
    ct[idx] = c; st[idx] = s;
}

__global__ void rope_apply_kernel(float* __restrict__ qkv, const int* __restrict__ pos,
                                  const float* __restrict__ ct, const float* __restrict__ st)
{
    int idx = blockIdx.x * blockDim.x + threadIdx.x;
    if (idx >= MTOT * 40 * 64) return;
    int j   = idx & 63;
    int hh  = (idx >> 6) % 40;
    int row = idx / (64 * 40);
    int p   = pos[row];
    float c = ct[p * 64 + j], s = st[p * 64 + j];
    int col = hh < 32 ? hh * 128 : 4096 + (hh - 32) * 128;
    float* ptr = qkv + (size_t)row * QKVN + col + j;
    float x1 = ptr[0], x2 = ptr[64];
    ptr[0]  = x1 * c - x2 * s;
    ptr[64] = x1 * s + x2 * c;
}

// ======================= split-bf16 mma.sync GEMM =======================
// C[M,N](+bias) = (Ahi+Alo)[m][k] @ (Bhi+Blo)[n][k]^T in fp32.
// 128x128 CTA tile, 8 warps (2x4), warp tile 64x32, K chunk 32,
// 3-stage cp.async pipeline, 3 MMA passes (hh, lh, hl).
__device__ __forceinline__ void g_load_stage(uint32_t sbase, int tid,
    const __nv_bfloat16* __restrict__ Ahi, const __nv_bfloat16* __restrict__ Alo,
    const __nv_bfloat16* __restrict__ Bhi, const __nv_bfloat16* __restrict__ Blo,
    int m0, int n0, int k0, int K)
{
    #pragma unroll
    for (int op = 0; op < 4; op++) {
        const __nv_bfloat16* src = op == 0 ? Ahi : op == 1 ? Alo : op == 2 ? Bhi : Blo;
        int row0 = (op < 2) ? m0 : n0;
        #pragma unroll
        for (int h = 0; h < 2; h++) {
            int ch = h * 256 + tid;
            int r = ch >> 2, c = ch & 3;
            const void* g = src + (size_t)(row0 + r) * K + k0 + c * 8;
            cp16(sbase + op * OP_BYTES + tile_off(r, c), g);
        }
    }
}

__global__ void __launch_bounds__(256) gemm_mma_kernel(
    const __nv_bfloat16* __restrict__ Ahi, const __nv_bfloat16* __restrict__ Alo,
    const __nv_bfloat16* __restrict__ Bhi, const __nv_bfloat16* __restrict__ Blo,
    const float* __restrict__ bias, float* __restrict__ C, int K, int ldc)
{
    extern __shared__ char sm[];
    const uint32_t smb = smem_u32(sm);
    const int tid  = threadIdx.x;
    const int wid  = tid >> 5, lane = tid & 31;
    const int wm   = wid >> 2, wn = wid & 3;     // 2 x 4 warp grid
    const int m0   = blockIdx.y * GMT;
    const int n0   = blockIdx.x * GNT;
    const int NC   = K / GKC;

    float acc[4][4][4];
    #pragma unroll
    for (int mt = 0; mt < 4; mt++)
        #pragma unroll
        for (int nt = 0; nt < 4; nt++)
            #pragma unroll
            for (int e = 0; e < 4; e++) acc[mt][nt][e] = 0.f;

    // prologue: stages 0 .. GSTAGES-2
    #pragma unroll
    for (int s = 0; s < GSTAGES - 1; s++) {
        g_load_stage(smb + s * STG_BYTES, tid, Ahi, Alo, Bhi, Blo, m0, n0, s * GKC, K);
        CP_COMMIT();
    }

    for (int c = 0; c < NC; c++) {
        CP_WAIT(GSTAGES - 2);
        __syncthreads();

        int nc = c + GSTAGES - 1;
        if (nc < NC)
            g_load_stage(smb + (nc % GSTAGES) * STG_BYTES, tid,
                         Ahi, Alo, Bhi, Blo, m0, n0, nc * GKC, K);
        CP_COMMIT();

        const uint32_t sb = smb + (c % GSTAGES) * STG_BYTES;
        #pragma unroll
        for (int ks = 0; ks < 2; ks++) {
            uint32_t ah[4][4], al[4][4], bh[4][2], bl[4][2];
            #pragma unroll
            for (int mt = 0; mt < 4; mt++) {
                int r  = wm * 64 + mt * 16 + (lane & 15);
                int cv = 2 * ks + (lane >> 4);
                uint32_t off = tile_off(r, cv);
                ldsm4(ah[mt][0], ah[mt][1], ah[mt][2], ah[mt][3], sb + off);
                ldsm4(al[mt][0], al[mt][1], al[mt][2], al[mt][3], sb + OP_BYTES + off);
            }
            #pragma unroll
            for (int np = 0; np < 2; np++) {
                int r  = wn * 32 + np * 16 + (lane & 7) + ((lane >> 4) << 3);
                int cv = 2 * ks + ((lane >> 3) & 1);
                uint32_t off = tile_off(r, cv);
                ldsm4(bh[np*2][0], bh[np*2][1], bh[np*2+1][0], bh[np*2+1][1],
                      sb + 2 * OP_BYTES + off);
                ldsm4(bl[np*2][0], bl[np*2][1], bl[np*2+1][0], bl[np*2+1][1],
                      sb + 3 * OP_BYTES + off);
            }
            #pragma unroll
            for (int mt = 0; mt < 4; mt++)
                #pragma unroll
                for (int nt = 0; nt < 4; nt++) {
                    mma_bf16(acc[mt][nt], ah[mt], bh[nt]);
                    mma_bf16(acc[mt][nt], al[mt], bh[nt]);
                    mma_bf16(acc[mt][nt], ah[mt], bl[nt]);
                }
        }
    }

    // epilogue
    const int tr = lane >> 2, tc = (lane & 3) * 2;
    #pragma unroll
    for (int mt = 0; mt < 4; mt++) {
        #pragma unroll
        for (int nt = 0; nt < 4; nt++) {
            int row = m0 + wm * 64 + mt * 16 + tr;
            int col = n0 + wn * 32 + nt * 8 + tc;
            float b0 = 0.f, b1 = 0.f;
            if (bias) { b0 = bias[col]; b1 = bias[col + 1]; }
            float2 v0 = make_float2(acc[mt][nt][0] + b0, acc[mt][nt][1] + b1);
            float2 v1 = make_float2(acc[mt][nt][2] + b0, acc[mt][nt][3] + b1);
            *(float2*)&C[(size_t)row * ldc + col]       = v0;
            *(float2*)&C[(size_t)(row + 8) * ldc + col] = v1;
        }
    }
}

// ======================= Flash attention (fp32) =======================
__global__ void __launch_bounds__(256) flash_kernel(
    const float* __restrict__ qkv, float* __restrict__ ao)
{
    extern __shared__ float smem[];
    float* Qt = smem;
    float* Kt = Qt + HDIM * QSTR;
    float* Vs = Kt + HDIM * KSTR;
    float* Pt = Vs + BK * HDIM;

    const int tid = threadIdx.x;
    const int tx  = tid & 15;
    const int ty  = tid >> 4;
    const int qt0 = blockIdx.x * BQ;
    const int h   = blockIdx.y;
    const int b   = blockIdx.z;
    const int kvh = h >> 2;
    const float scale = 0.08838834764831843f;

    for (int idx = tid; idx < 32 * BQ; idx += 256) {
        int i  = idx & (BQ - 1);
        int d4 = (idx >> 6) << 2;
        float4 val = *(const float4*)(qkv + (size_t)(b*SEQ + qt0 + i) * QKVN + h * 128 + d4);
        Qt[(d4+0)*QSTR + i] = val.x * scale;
        Qt[(d4+1)*QSTR + i] = val.y * scale;
        Qt[(d4+2)*QSTR + i] = val.z * scale;
        Qt[(d4+3)*QSTR + i] = val.w * scale;
    }

    float m[4], l[4], acc[4][8];
    #pragma unroll
    for (int i = 0; i < 4; i++) {
        m[i] = -1e30f; l[i] = 0.f;
        #pragma unroll
        for (int j = 0; j < 8; j++) acc[i][j] = 0.f;
    }

    const int ntiles = qt0 / BK + 1;
    for (int kt = 0; kt < ntiles; kt++) {
        const int kt0 = kt * BK;

        for (int idx = tid; idx < 32 * BK; idx += 256) {
            int j  = idx & (BK - 1);
            int d4 = (idx >> 6) << 2;
            float4 kk = *(const float4*)(qkv + (size_t)(b*SEQ + kt0 + j) * QKVN + 4096 + kvh * 128 + d4);
            Kt[(d4+0)*KSTR + j] = kk.x;
            Kt[(d4+1)*KSTR + j] = kk.y;
            Kt[(d4+2)*KSTR + j] = kk.z;
            Kt[(d4+3)*KSTR + j] = kk.w;
        }
        for (int idx = tid; idx < 32 * BK; idx += 256) {
            int j  = idx >> 5;
            int d4 = (idx & 31) << 2;
            *(float4*)&Vs[j*HDIM + d4] =
                *(const float4*)(qkv + (size_t)(b*SEQ + kt0 + j) * QKVN + 5120 + kvh * 128 + d4);
        }
        __syncthreads();

        float s[4][4];
        #pragma unroll
        for (int i = 0; i < 4; i++)
            #pragma unroll
            for (int j = 0; j < 4; j++) s[i][j] = 0.f;

        #pragma unroll 8
        for (int d = 0; d < HDIM; d++) {
            float4 aq  = *(const float4*)&Qt[d*QSTR + ty*4];
            float4 bk4 = *(const float4*)&Kt[d*KSTR + tx*4];
            float a[4]  = {aq.x, aq.y, aq.z, aq.w};
            float bb[4] = {bk4.x, bk4.y, bk4.z, bk4.w};
            #pragma unroll
            for (int i = 0; i < 4; i++)
                #pragma unroll
                for (int j = 0; j < 4; j++)
                    s[i][j] += a[i] * bb[j];
        }

        if (kt == ntiles - 1) {
            #pragma unroll
            for (int ii = 0; ii < 4; ii++)
                #pragma unroll
                for (int jj = 0; jj < 4; jj++)
                    if (kt0 + tx*4 + jj > qt0 + ty*4 + ii) s[ii][jj] = -1e30f;
        }

        #pragma unroll
        for (int ii = 0; ii < 4; ii++) {
            float tm = fmaxf(fmaxf(s[ii][0], s[ii][1]), fmaxf(s[ii][2], s[ii][3]));
            #pragma unroll
            for (int o = 8; o > 0; o >>= 1)
                tm = fmaxf(tm, __shfl_xor_sync(0xffffffffu, tm, o, 16));
            float mn = fmaxf(m[ii], tm);
            float al = __expf(m[ii] - mn);
            float rs = 0.f;
            #pragma unroll
            for (int jj = 0; jj < 4; jj++) {
                float p = __expf(s[ii][jj] - mn);
                s[ii][jj] = p;
                rs += p;
            }
            #pragma unroll
            for (int o = 8; o > 0; o >>= 1)
                rs += __shfl_xor_sync(0xffffffffu, rs, o, 16);
            l[ii] = l[ii]*al + rs;
            m[ii] = mn;
            #pragma unroll
            for (int jj = 0; jj < 8; jj++) acc[ii][jj] *= al;
        }

        #pragma unroll
        for (int jj = 0; jj < 4; jj++) {
            float4 pv = make_float4(s[0][jj], s[1][jj], s[2][jj], s[3][jj]);
            *(float4*)&Pt[(tx*4 + jj)*PSTR + ty*4] = pv;
        }
        __syncthreads();

        #pragma unroll 4
        for (int j = 0; j < BK; j++) {
            float4 pa = *(const float4*)&Pt[j*PSTR + ty*4];
            float4 v0 = *(const float4*)&Vs[j*HDIM + tx*8];
            float4 v1 = *(const float4*)&Vs[j*HDIM + tx*8 + 4];
            float pr[4] = {pa.x, pa.y, pa.z, pa.w};
            #pragma unroll
            for (int ii = 0; ii < 4; ii++) {
                acc[ii][0] += pr[ii]*v0.x; acc[ii][1] += pr[ii]*v0.y;
                acc[ii][2] += pr[ii]*v0.z; acc[ii][3] += pr[ii]*v0.w;
                acc[ii][4] += pr[ii]*v1.x; acc[ii][5] += pr[ii]*v1.y;
                acc[ii][6] += pr[ii]*v1.z; acc[ii][7] += pr[ii]*v1.w;
            }
        }
        __syncthreads();
    }

    #pragma unroll
    for (int ii = 0; ii < 4; ii++) {
        float inv = 1.f / l[ii];
        int qi = qt0 + ty*4 + ii;
        float* dst = ao + (((size_t)(b*SEQ + qi)*NH + h) << 7) + tx*8;
        float4 o0 = make_float4(acc[ii][0]*inv, acc[ii][1]*inv, acc[ii][2]*inv, acc[ii][3]*inv);
        float4 o1 = make_float4(acc[ii][4]*inv, acc[ii][5]*inv, acc[ii][6]*inv, acc[ii][7]*inv);
        *(float4*)dst       = o0;
        *(float4*)(dst + 4) = o1;
    }
}

// ======================= Launch =======================
extern "C" void kernel_launch(void* const* d_in, const int* in_sizes, int n_in,
                              void* d_out, int out_size)
{
    const float* hidden = (const float*)d_in[0];
    const int*   pos    = (const int*)  d_in[1];
    const float* wq     = (const float*)d_in[2];
    const float* bq     = (const float*)d_in[3];
    const float* wk     = (const float*)d_in[4];
    const float* bk     = (const float*)d_in[5];
    const float* wv     = (const float*)d_in[6];
    const float* bv     = (const float*)d_in[7];
    const float* wo     = (const float*)d_in[8];
    float* out = (float*)d_out;

    __nv_bfloat16 *hh, *hl, *qh, *ql, *oh, *ol, *aoh, *aol;
    float *qkv, *ao, *bias, *ct, *st;
    cudaGetSymbolAddress((void**)&hh,  g_hid_hi);
    cudaGetSymbolAddress((void**)&hl,  g_hid_lo);
    cudaGetSymbolAddress((void**)&qh,  g_wqkv_hi);
    cudaGetSymbolAddress((void**)&ql,  g_wqkv_lo);
    cudaGetSymbolAddress((void**)&oh,  g_wo_hi);
    cudaGetSymbolAddress((void**)&ol,  g_wo_lo);
    cudaGetSymbolAddress((void**)&aoh, g_ao_hi);
    cudaGetSymbolAddress((void**)&aol, g_ao_lo);
    cudaGetSymbolAddress((void**)&qkv, g_qkv);
    cudaGetSymbolAddress((void**)&ao,  g_ao);
    cudaGetSymbolAddress((void**)&bias,g_bias);
    cudaGetSymbolAddress((void**)&ct,  g_cos);
    cudaGetSymbolAddress((void**)&st,  g_sin);

    cudaFuncSetAttribute(gemm_mma_kernel, cudaFuncAttributeMaxDynamicSharedMemorySize, GEMM_SMEM);
    size_t fsm = (size_t)(HDIM*QSTR + HDIM*KSTR + BK*HDIM + BK*PSTR) * sizeof(float);
    cudaFuncSetAttribute(flash_kernel, cudaFuncAttributeMaxDynamicSharedMemorySize, (int)fsm);

    // conversions
    int n4h = MTOT * DMODEL / 4;
    conv_split_kernel<<<(n4h + 255)/256, 256>>>((const float4*)hidden, (uint2*)hh, (uint2*)hl, n4h);
    conv_wqkv_kernel<<<dim3(DMODEL/32, QKVN/32), dim3(32,8)>>>(wq, wk, wv, qh, ql);
    conv_wo_kernel  <<<dim3(DMODEL/32, DMODEL/32), dim3(32,8)>>>(wo, oh, ol);
    concat_bias_kernel<<<(QKVN + 255)/256, 256>>>(bq, bk, bv, bias);
    rope_table_kernel<<<(SEQ*64 + 255)/256, 256>>>(ct, st);

    // fused QKV projection (mma.sync tensor cores)
    gemm_mma_kernel<<<dim3(QKVN/GNT, MTOT/GMT), 256, GEMM_SMEM>>>(hh, hl, qh, ql, bias, qkv, DMODEL, QKVN);

    // RoPE
    rope_apply_kernel<<<(MTOT*40*64 + 255)/256, 256>>>(qkv, pos, ct, st);

    // flash attention (fp32)
    flash_kernel<<<dim3(SEQ/BQ, NH, BATCH), 256, fsm>>>(qkv, ao);

    // split attention output, then out-projection
    conv_split_kernel<<<(n4h + 255)/256, 256>>>((const float4*)ao, (uint2*)aoh, (uint2*)aol, n4h);
    gemm_mma_kernel<<<dim3(DMODEL/GNT, MTOT/GMT), 256, GEMM_SMEM>>>(aoh, aol, oh, ol, nullptr, out, DMODEL, DMODEL);
}

// round 4
// speedup vs baseline: 3.1422x; 1.6866x over previous
#include <cuda_runtime.h>
#include <cuda_bf16.h>
#include <cstdint>
#include <math.h>

// Problem constants
#define BATCH  2
#define SEQ    2048
#define DMODEL 4096
#define NH     32
#define NKV    8
#define HDIM   128
#define MTOT   (BATCH*SEQ)
#define QKVN   6144
#define SCALE  0.08838834764831843f   // 1/sqrt(128)

// mma.sync GEMM tiling (validated R3)
#define GMT 128
#define GNT 128
#define GKC 32
#define GSTAGES 3
#define OP_BYTES  (128*GKC*2)
#define STG_BYTES (4*OP_BYTES)
#define GEMM_SMEM (GSTAGES*STG_BYTES)

// flash tiling
#define FBQ 128
#define FBK 64
#define FLASH_SMEM 196608   // 192KB

// -------- scratch --------
__device__ __align__(16) __nv_bfloat16 g_hid_hi [(size_t)MTOT*DMODEL];
__device__ __align__(16) __nv_bfloat16 g_hid_lo [(size_t)MTOT*DMODEL];
__device__ __align__(16) __nv_bfloat16 g_wqkv_hi[(size_t)QKVN*DMODEL];
__device__ __align__(16) __nv_bfloat16 g_wqkv_lo[(size_t)QKVN*DMODEL];
__device__ __align__(16) __nv_bfloat16 g_wo_hi  [(size_t)DMODEL*DMODEL];
__device__ __align__(16) __nv_bfloat16 g_wo_lo  [(size_t)DMODEL*DMODEL];
__device__ __align__(16) float g_qkv [(size_t)MTOT*QKVN];
__device__ __align__(16) __nv_bfloat16 g_q_hi [(size_t)MTOT*NH*HDIM];
__device__ __align__(16) __nv_bfloat16 g_q_lo [(size_t)MTOT*NH*HDIM];
__device__ __align__(16) __nv_bfloat16 g_k_hi [(size_t)MTOT*NKV*HDIM];
__device__ __align__(16) __nv_bfloat16 g_k_lo [(size_t)MTOT*NKV*HDIM];
__device__ __align__(16) __nv_bfloat16 g_vt_hi[(size_t)BATCH*NKV*HDIM*SEQ];
__device__ __align__(16) __nv_bfloat16 g_vt_lo[(size_t)BATCH*NKV*HDIM*SEQ];
__device__ __align__(16) __nv_bfloat16 g_ao_hi[(size_t)MTOT*DMODEL];
__device__ __align__(16) __nv_bfloat16 g_ao_lo[(size_t)MTOT*DMODEL];
__device__ float g_bias[QKVN];
__device__ float g_cos[SEQ*64];
__device__ float g_sin[SEQ*64];

// ======================= helpers =======================
__device__ __forceinline__ uint32_t smem_u32(const void* p) {
    uint32_t a;
    asm("{ .reg .u64 t; cvta.to.shared.u64 t, %1; cvt.u32.u64 %0, t; }" : "=r"(a) : "l"(p));
    return a;
}
__device__ __forceinline__ void cp16(uint32_t s, const void* g) {
    asm volatile("cp.async.cg.shared.global [%0], [%1], 16;" :: "r"(s), "l"(g));
}
#define CP_COMMIT()  asm volatile("cp.async.commit_group;" ::: "memory")
#define CP_WAIT(n)   asm volatile("cp.async.wait_group %0;" :: "n"(n) : "memory")

__device__ __forceinline__ void ldsm4(uint32_t& r0, uint32_t& r1, uint32_t& r2, uint32_t& r3,
                                      uint32_t a) {
    asm volatile("ldmatrix.sync.aligned.m8n8.x4.shared.b16 {%0,%1,%2,%3}, [%4];"
        : "=r"(r0), "=r"(r1), "=r"(r2), "=r"(r3) : "r"(a));
}
__device__ __forceinline__ void mma_bf16(float* c, const uint32_t* a, const uint32_t* b) {
    asm volatile("mma.sync.aligned.m16n8k16.row.col.f32.bf16.bf16.f32 "
        "{%0,%1,%2,%3}, {%4,%5,%6,%7}, {%8,%9}, {%0,%1,%2,%3};"
        : "+f"(c[0]), "+f"(c[1]), "+f"(c[2]), "+f"(c[3])
        : "r"(a[0]), "r"(a[1]), "r"(a[2]), "r"(a[3]), "r"(b[0]), "r"(b[1]));
}
__device__ __forceinline__ void split2(float x, unsigned short& h, unsigned short& l) {
    __nv_bfloat16 hb = __float2bfloat16(x);
    float hf = __bfloat162float(hb);
    __nv_bfloat16 lb = __float2bfloat16(x - hf);
    h = __bfloat16_as_ushort(hb);
    l = __bfloat16_as_ushort(lb);
}
// pack two fp32 into bf16x2 hi and residual-lo regs
__device__ __forceinline__ void packsplit(float x0, float x1, uint32_t& h, uint32_t& l) {
    __nv_bfloat16 h0 = __float2bfloat16(x0), h1 = __float2bfloat16(x1);
    float r0 = x0 - __bfloat162float(h0);
    float r1 = x1 - __bfloat162float(h1);
    __nv_bfloat16 l0 = __float2bfloat16(r0), l1 = __float2bfloat16(r1);
    h = (uint32_t)__bfloat16_as_ushort(h0) | ((uint32_t)__bfloat16_as_ushort(h1) << 16);
    l = (uint32_t)__bfloat16_as_ushort(l0) | ((uint32_t)__bfloat16_as_ushort(l1) << 16);
}
// gemm tile addressing (64B rows, validated)
__device__ __forceinline__ uint32_t tile_off(int r, int c) {
    return (uint32_t)(r * 64 + ((c ^ ((r >> 1) & 3)) << 4));
}
// flash smem addressing: 256B rows (Q,K), 128B rows (Vt)
#define QOFF(r,c) ((uint32_t)((r)*256 + (((c) ^ ((r)&7))<<4)))
#define VOFF(r,c) ((uint32_t)((r)*128 + (((c) ^ ((r)&7))<<4)))

// ======================= conversion kernels =======================
__global__ void conv_split_kernel(const float4* __restrict__ src,
                                  uint2* __restrict__ hi, uint2* __restrict__ lo, int n4)
{
    int i = blockIdx.x * blockDim.x + threadIdx.x;
    if (i >= n4) return;
    float4 v = src[i];
    float xs[4] = {v.x, v.y, v.z, v.w};
    unsigned short hs[4], ls[4];
    #pragma unroll
    for (int j = 0; j < 4; j++) split2(xs[j], hs[j], ls[j]);
    hi[i] = make_uint2((uint32_t)hs[0] | ((uint32_t)hs[1] << 16),
                       (uint32_t)hs[2] | ((uint32_t)hs[3] << 16));
    lo[i] = make_uint2((uint32_t)ls[0] | ((uint32_t)ls[1] << 16),
                       (uint32_t)ls[2] | ((uint32_t)ls[3] << 16));
}

// merged weight transpose-convert: wqkv (by<192) and wo (by>=192)
__global__ void conv_weights_kernel(const float* __restrict__ wq, const float* __restrict__ wk,
                                    const float* __restrict__ wv, const float* __restrict__ wo,
                                    __nv_bfloat16* __restrict__ qkvhi, __nv_bfloat16* __restrict__ qkvlo,
                                    __nv_bfloat16* __restrict__ wohi,  __nv_bfloat16* __restrict__ wolo)
{
    __shared__ float t[32][33];
    int k0 = blockIdx.x * 32;
    int by = blockIdx.y;
    int tx = threadIdx.x, ty = threadIdx.y;
    const float* src; int ld, nl, n0;
    __nv_bfloat16 *dhi, *dlo;
    if (by < 192) {
        n0 = by * 32;
        if (n0 < 4096)       { src = wq; ld = 4096; nl = n0; }
        else if (n0 < 5120)  { src = wk; ld = 1024; nl = n0 - 4096; }
        else                 { src = wv; ld = 1024; nl = n0 - 5120; }
        dhi = qkvhi; dlo = qkvlo;
    } else {
        n0 = (by - 192) * 32; src = wo; ld = DMODEL; nl = n0;
        dhi = wohi; dlo = wolo;
    }
    #pragma unroll
    for (int r = 0; r < 4; r++)
        t[ty + 8*r][tx] = src[(size_t)(k0 + ty + 8*r) * ld + nl + tx];
    __syncthreads();
    #pragma unroll
    for (int r = 0; r < 4; r++) {
        float x = t[tx][ty + 8*r];
        unsigned short h, l; split2(x, h, l);
        size_t o = (size_t)(n0 + ty + 8*r) * DMODEL + k0 + tx;
        dhi[o] = __ushort_as_bfloat16(h);
        dlo[o] = __ushort_as_bfloat16(l);
    }
}

// merged bias concat + rope cos/sin table
__global__ void bias_table_kernel(const float* bq, const float* bk, const float* bv,
                                  float* __restrict__ bias,
                                  float* __restrict__ ct, float* __restrict__ st)
{
    int i = blockIdx.x * blockDim.x + threadIdx.x;
    if (i < QKVN) {
        bias[i] = i < 4096 ? bq[i] : (i < 5120 ? bk[i - 4096] : bv[i - 5120]);
    } else if (i < QKVN + SEQ*64) {
        int idx = i - QKVN;
        int j = idx & 63, p = idx >> 6;
        double freq = exp2(-(double)j * 0.31143075889569021);
        double ang  = (double)p * freq;
        double kq   = rint(ang * 0.15915494309189533577);
        float  a    = (float)(ang - kq * 6.28318530717958647693);
        float c, s;
        __sincosf(a, &s, &c);
        ct[idx] = c; st[idx] = s;
    }
}

// RoPE: read fp32 qkv, rotate, write bf16 hi/lo Q (pre-scaled) and K buffers
__global__ void rope_bf16_kernel(const float* __restrict__ qkv, const int* __restrict__ pos,
                                 const float* __restrict__ ct, const float* __restrict__ st,
                                 __nv_bfloat16* __restrict__ qhi, __nv_bfloat16* __restrict__ qlo,
                                 __nv_bfloat16* __restrict__ khi, __nv_bfloat16* __restrict__ klo)
{
    int idx = blockIdx.x * blockDim.x + threadIdx.x;
    if (idx >= MTOT * 40 * 64) return;
    int j   = idx & 63;
    int hh  = (idx >> 6) % 40;
    int row = idx / (64 * 40);
    int p   = pos[row];
    float c = ct[p*64 + j], s = st[p*64 + j];
    if (hh < 32) {
        const float* ptr = qkv + (size_t)row * QKVN + hh * 128 + j;
        float x1 = ptr[0], x2 = ptr[64];
        float y1 = (x1*c - x2*s) * SCALE;
        float y2 = (x1*s + x2*c) * SCALE;
        size_t o = ((size_t)row * 32 + hh) * 128 + j;
        unsigned short h1,l1,h2,l2; split2(y1,h1,l1); split2(y2,h2,l2);
        qhi[o]    = __ushort_as_bfloat16(h1); qlo[o]    = __ushort_as_bfloat16(l1);
        qhi[o+64] = __ushort_as_bfloat16(h2); qlo[o+64] = __ushort_as_bfloat16(l2);
    } else {
        int kvh = hh - 32;
        const float* ptr = qkv + (size_t)row * QKVN + 4096 + kvh * 128 + j;
        float x1 = ptr[0], x2 = ptr[64];
        float y1 = x1*c - x2*s;
        float y2 = x1*s + x2*c;
        size_t o = ((size_t)row * 8 + kvh) * 128 + j;
        unsigned short h1,l1,h2,l2; split2(y1,h1,l1); split2(y2,h2,l2);
        khi[o]    = __ushort_as_bfloat16(h1); klo[o]    = __ushort_as_bfloat16(l1);
        khi[o+64] = __ushort_as_bfloat16(h2); klo[o+64] = __ushort_as_bfloat16(l2);
    }
}

// V transpose-convert: qkv v region [b,s,kvh,d] fp32 -> [b,kvh,d,s] bf16 hi/lo
__global__ void vconv_kernel(const float* __restrict__ qkv,
                             __nv_bfloat16* __restrict__ vth, __nv_bfloat16* __restrict__ vtl)
{
    __shared__ float t[32][33];
    int s0 = blockIdx.x * 32, d0 = blockIdx.y * 32;
    int bz = blockIdx.z; int b = bz >> 3, kvh = bz & 7;
    int tx = threadIdx.x, ty = threadIdx.y;
    #pragma unroll
    for (int r = 0; r < 4; r++)
        t[ty + 8*r][tx] = qkv[(size_t)(b*SEQ + s0 + ty + 8*r) * QKVN + 5120 + kvh*128 + d0 + tx];
    __syncthreads();
    #pragma unroll
    for (int r = 0; r < 4; r++) {
        float x = t[tx][ty + 8*r];
        unsigned short h, l; split2(x, h, l);
        size_t o = ((size_t)(b*8 + kvh) * 128 + d0 + ty + 8*r) * SEQ + s0 + tx;
        vth[o] = __ushort_as_bfloat16(h);
        vtl[o] = __ushort_as_bfloat16(l);
    }
}

// ======================= split-bf16 mma.sync GEMM (validated R3) =======================
__device__ __forceinline__ void g_load_stage(uint32_t sbase, int tid,
    const __nv_bfloat16* __restrict__ Ahi, const __nv_bfloat16* __restrict__ Alo,
    const __nv_bfloat16* __restrict__ Bhi, const __nv_bfloat16* __restrict__ Blo,
    int m0, int n0, int k0, int K)
{
    #pragma unroll
    for (int op = 0; op < 4; op++) {
        const __nv_bfloat16* src = op == 0 ? Ahi : op == 1 ? Alo : op == 2 ? Bhi : Blo;
        int row0 = (op < 2) ? m0 : n0;
        #pragma unroll
        for (int h = 0; h < 2; h++) {
            int ch = h * 256 + tid;
            int r = ch >> 2, c = ch & 3;
            const void* g = src + (size_t)(row0 + r) * K + k0 + c * 8;
            cp16(sbase + op * OP_BYTES + tile_off(r, c), g);
        }
    }
}

__global__ void __launch_bounds__(256) gemm_mma_kernel(
    const __nv_bfloat16* __restrict__ Ahi, const __nv_bfloat16* __restrict__ Alo,
    const __nv_bfloat16* __restrict__ Bhi, const __nv_bfloat16* __restrict__ Blo,
    const float* __restrict__ bias, float* __restrict__ C, int K, int ldc)
{
    extern __shared__ char sm[];
    const uint32_t smb = smem_u32(sm);
    const int tid  = threadIdx.x;
    const int wid  = tid >> 5, lane = tid & 31;
    const int wm   = wid >> 2, wn = wid & 3;
    const int m0   = blockIdx.y * GMT;
    const int n0   = blockIdx.x * GNT;
    const int NC   = K / GKC;

    float acc[4][4][4];
    #pragma unroll
    for (int mt = 0; mt < 4; mt++)
        #pragma unroll
        for (int nt = 0; nt < 4; nt++)
            #pragma unroll
            for (int e = 0; e < 4; e++) acc[mt][nt][e] = 0.f;

    #pragma unroll
    for (int s = 0; s < GSTAGES - 1; s++) {
        g_load_stage(smb + s * STG_BYTES, tid, Ahi, Alo, Bhi, Blo, m0, n0, s * GKC, K);
        CP_COMMIT();
    }

    for (int c = 0; c < NC; c++) {
        CP_WAIT(GSTAGES - 2);
        __syncthreads();

        int nc = c + GSTAGES - 1;
        if (nc < NC)
            g_load_stage(smb + (nc % GSTAGES) * STG_BYTES, tid,
                         Ahi, Alo, Bhi, Blo, m0, n0, nc * GKC, K);
        CP_COMMIT();

        const uint32_t sb = smb + (c % GSTAGES) * STG_BYTES;
        #pragma unroll
        for (int ks = 0; ks < 2; ks++) {
            uint32_t ah[4][4], al[4][4], bh[4][2], bl[4][2];
            #pragma unroll
            for (int mt = 0; mt < 4; mt++) {
                int r  = wm * 64 + mt * 16 + (lane & 15);
                int cv = 2 * ks + (lane >> 4);
                uint32_t off = tile_off(r, cv);
                ldsm4(ah[mt][0], ah[mt][1], ah[mt][2], ah[mt][3], sb + off);
                ldsm4(al[mt][0], al[mt][1], al[mt][2], al[mt][3], sb + OP_BYTES + off);
            }
            #pragma unroll
            for (int np = 0; np < 2; np++) {
                int r  = wn * 32 + np * 16 + (lane & 7) + ((lane >> 4) << 3);
                int cv = 2 * ks + ((lane >> 3) & 1);
                uint32_t off = tile_off(r, cv);
                ldsm4(bh[np*2][0], bh[np*2][1], bh[np*2+1][0], bh[np*2+1][1],
                      sb + 2 * OP_BYTES + off);
                ldsm4(bl[np*2][0], bl[np*2][1], bl[np*2+1][0], bl[np*2+1][1],
                      sb + 3 * OP_BYTES + off);
            }
            #pragma unroll
            for (int mt = 0; mt < 4; mt++)
                #pragma unroll
                for (int nt = 0; nt < 4; nt++) {
                    mma_bf16(acc[mt][nt], ah[mt], bh[nt]);
                    mma_bf16(acc[mt][nt], al[mt], bh[nt]);
                    mma_bf16(acc[mt][nt], ah[mt], bl[nt]);
                }
        }
    }

    const int tr = lane >> 2, tc = (lane & 3) * 2;
    #pragma unroll
    for (int mt = 0; mt < 4; mt++) {
        #pragma unroll
        for (int nt = 0; nt < 4; nt++) {
            int row = m0 + wm * 64 + mt * 16 + tr;
            int col = n0 + wn * 32 + nt * 8 + tc;
            float b0 = 0.f, b1 = 0.f;
            if (bias) { b0 = bias[col]; b1 = bias[col + 1]; }
            float2 v0 = make_float2(acc[mt][nt][0] + b0, acc[mt][nt][1] + b1);
            float2 v1 = make_float2(acc[mt][nt][2] + b0, acc[mt][nt][3] + b1);
            *(float2*)&C[(size_t)row * ldc + col]       = v0;
            *(float2*)&C[(size_t)(row + 8) * ldc + col] = v1;
        }
    }
}

// ======================= flash attention: split-bf16 HMMA =======================
__device__ __forceinline__ void f_load_kv(uint32_t kb, uint32_t vbuf, int tid,
    const __nv_bfloat16* __restrict__ kh, const __nv_bfloat16* __restrict__ kl,
    const __nv_bfloat16* __restrict__ vth, const __nv_bfloat16* __restrict__ vtl,
    int b, int kvh, int kt0)
{
    #pragma unroll
    for (int it = 0; it < 4; it++) {
        int i = it * 256 + tid;
        int r = i >> 4, c = i & 15;
        size_t go = ((size_t)(b*SEQ + kt0 + r) * NKV + kvh) * HDIM + c * 8;
        cp16(kb + QOFF(r, c),         kh + go);
        cp16(kb + 16384 + QOFF(r, c), kl + go);
    }
    #pragma unroll
    for (int it = 0; it < 4; it++) {
        int i = it * 256 + tid;
        int r = i >> 3, c = i & 7;
        size_t go = ((size_t)(b*NKV + kvh) * HDIM + r) * SEQ + kt0 + c * 8;
        cp16(vbuf + VOFF(r, c),         vth + go);
        cp16(vbuf + 16384 + VOFF(r, c), vtl + go);
    }
}

__global__ void __launch_bounds__(256) flash_mma_kernel(
    const __nv_bfloat16* __restrict__ qh_g, const __nv_bfloat16* __restrict__ ql_g,
    const __nv_bfloat16* __restrict__ kh_g, const __nv_bfloat16* __restrict__ kl_g,
    const __nv_bfloat16* __restrict__ vth_g, const __nv_bfloat16* __restrict__ vtl_g,
    __nv_bfloat16* __restrict__ aoh, __nv_bfloat16* __restrict__ aol)
{
    extern __shared__ char sm[];
    const uint32_t smb = smem_u32(sm);
    const uint32_t sQh = smb;                 // 32KB
    const uint32_t sQl = smb + 32768;         // 32KB
    const uint32_t sK  = smb + 65536;         // 2 bufs x (16KB hi + 16KB lo)
    const uint32_t sV  = smb + 131072;        // 2 bufs x (16KB hi + 16KB lo)

    const int tid  = threadIdx.x;
    const int w    = tid >> 5, lane = tid & 31;
    const int qt0  = blockIdx.x * FBQ;
    const int h    = blockIdx.y;
    const int b    = blockIdx.z;
    const int kvh  = h >> 2;
    const int nt   = qt0 / FBK + 2;

    // load Q tile (hi+lo)
    #pragma unroll
    for (int it = 0; it < 8; it++) {
        int i = it * 256 + tid;
        int r = i >> 4, c = i & 15;
        size_t go = ((size_t)(b*SEQ + qt0 + r) * NH + h) * HDIM + c * 8;
        cp16(sQh + QOFF(r, c), qh_g + go);
        cp16(sQl + QOFF(r, c), ql_g + go);
    }
    CP_COMMIT();
    f_load_kv(sK, sV, tid, kh_g, kl_g, vth_g, vtl_g, b, kvh, 0);
    CP_COMMIT();

    float O[16][4];
    #pragma unroll
    for (int i = 0; i < 16; i++)
        #pragma unroll
        for (int e = 0; e < 4; e++) O[i][e] = 0.f;
    float m0 = -1e30f, m1 = -1e30f, l0 = 0.f, l1 = 0.f;

    for (int kt = 0; kt < nt; kt++) {
        __syncthreads();
        if (kt + 1 < nt)
            f_load_kv(sK + ((kt+1)&1)*32768, sV + ((kt+1)&1)*32768, tid,
                      kh_g, kl_g, vth_g, vtl_g, b, kvh, (kt+1)*FBK);
        CP_COMMIT();
        CP_WAIT(1);
        __syncthreads();

        const uint32_t kb = sK + (kt&1)*32768;
        const uint32_t vb = sV + (kt&1)*32768;

        // ---- S = Q K^T (3-pass split) ----
        float s[8][4];
        #pragma unroll
        for (int i = 0; i < 8; i++)
            #pragma unroll
            for (int e = 0; e < 4; e++) s[i][e] = 0.f;

        #pragma unroll
        for (int ks = 0; ks < 8; ks++) {
            uint32_t ah[4], al[4];
            uint32_t qoff = QOFF(w*16 + (lane & 15), 2*ks + (lane >> 4));
            ldsm4(ah[0], ah[1], ah[2], ah[3], sQh + qoff);
            ldsm4(al[0], al[1], al[2], al[3], sQl + qoff);
            uint32_t bh[8][2], bl[8][2];
            #pragma unroll
            for (int np = 0; np < 4; np++) {
                uint32_t boff = QOFF(np*16 + (lane & 7) + ((lane >> 4) << 3),
                                     2*ks + ((lane >> 3) & 1));
                ldsm4(bh[np*2][0], bh[np*2][1], bh[np*2+1][0], bh[np*2+1][1], kb + boff);
                ldsm4(bl[np*2][0], bl[np*2][1], bl[np*2+1][0], bl[np*2+1][1], kb + 16384 + boff);
            }
            #pragma unroll
            for (int ntl = 0; ntl < 8; ntl++) {
                mma_bf16(s[ntl], ah, bh[ntl]);
                mma_bf16(s[ntl], al, bh[ntl]);
                mma_bf16(s[ntl], ah, bl[ntl]);
            }
        }

        // ---- causal mask (last two tiles only) ----
        if (kt >= nt - 2) {
            int r0 = qt0 + w*16 + (lane >> 2);
            int c0 = kt*FBK + (lane & 3)*2;
            #pragma unroll
            for (int ntl = 0; ntl < 8; ntl++) {
                int cb = c0 + ntl*8;
                if (cb     > r0)     s[ntl][0] = -1e30f;
                if (cb + 1 > r0)     s[ntl][1] = -1e30f;
                if (cb     > r0 + 8) s[ntl][2] = -1e30f;
                if (cb + 1 > r0 + 8) s[ntl][3] = -1e30f;
            }
        }

        // ---- online softmax ----
        float rm0 = -1e30f, rm1 = -1e30f;
        #pragma unroll
        for (int ntl = 0; ntl < 8; ntl++) {
            rm0 = fmaxf(rm0, fmaxf(s[ntl][0], s[ntl][1]));
            rm1 = fmaxf(rm1, fmaxf(s[ntl][2], s[ntl][3]));
        }
        rm0 = fmaxf(rm0, __shfl_xor_sync(0xffffffffu, rm0, 1));
        rm0 = fmaxf(rm0, __shfl_xor_sync(0xffffffffu, rm0, 2));
        rm1 = fmaxf(rm1, __shfl_xor_sync(0xffffffffu, rm1, 1));
        rm1 = fmaxf(rm1, __shfl_xor_sync(0xffffffffu, rm1, 2));
        float mn0 = fmaxf(m0, rm0), mn1 = fmaxf(m1, rm1);
        float a0 = __expf(m0 - mn0), a1 = __expf(m1 - mn1);
        float rs0 = 0.f, rs1 = 0.f;
        #pragma unroll
        for (int ntl = 0; ntl < 8; ntl++) {
            s[ntl][0] = __expf(s[ntl][0] - mn0);
            s[ntl][1] = __expf(s[ntl][1] - mn0);
            s[ntl][2] = __expf(s[ntl][2] - mn1);
            s[ntl][3] = __expf(s[ntl][3] - mn1);
            rs0 += s[ntl][0] + s[ntl][1];
            rs1 += s[ntl][2] + s[ntl][3];
        }
        rs0 += __shfl_xor_sync(0xffffffffu, rs0, 1);
        rs0 += __shfl_xor_sync(0xffffffffu, rs0, 2);
        rs1 += __shfl_xor_sync(0xffffffffu, rs1, 1);
        rs1 += __shfl_xor_sync(0xffffffffu, rs1, 2);
        l0 = l0*a0 + rs0; l1 = l1*a1 + rs1;
        m0 = mn0; m1 = mn1;
        #pragma unroll
        for (int i = 0; i < 16; i++) {
            O[i][0] *= a0; O[i][1] *= a0;
            O[i][2] *= a1; O[i][3] *= a1;
        }

        // ---- O += P V (3-pass split, P frags from accumulators) ----
        #pragma unroll
        for (int kk = 0; kk < 4; kk++) {
            uint32_t ph[4], pl[4];
            packsplit(s[2*kk][0],   s[2*kk][1],   ph[0], pl[0]);
            packsplit(s[2*kk][2],   s[2*kk][3],   ph[1], pl[1]);
            packsplit(s[2*kk+1][0], s[2*kk+1][1], ph[2], pl[2]);
            packsplit(s[2*kk+1][2], s[2*kk+1][3], ph[3], pl[3]);
            #pragma unroll
            for (int np = 0; np < 8; np++) {
                uint32_t vh0[2], vh1[2], vl0[2], vl1[2];
                uint32_t voff = VOFF(np*16 + (lane & 7) + ((lane >> 4) << 3),
                                     2*kk + ((lane >> 3) & 1));
                ldsm4(vh0[0], vh0[1], vh1[0], vh1[1], vb + voff);
                ldsm4(vl0[0], vl0[1], vl1[0], vl1[1], vb + 16384 + voff);
                mma_bf16(O[np*2],   ph, vh0);
                mma_bf16(O[np*2],   pl, vh0);
                mma_bf16(O[np*2],   ph, vl0);
                mma_bf16(O[np*2+1], ph, vh1);
                mma_bf16(O[np*2+1], pl, vh1);
                mma_bf16(O[np*2+1], ph, vl1);
            }
        }
    }

    // ---- epilogue: normalize + split + write ao hi/lo ----
    float inv0 = 1.f / l0, inv1 = 1.f / l1;
    int r0 = qt0 + w*16 + (lane >> 2);
    size_t base0 = ((size_t)(b*SEQ + r0)     * NH + h) * HDIM;
    size_t base1 = ((size_t)(b*SEQ + r0 + 8) * NH + h) * HDIM;
    #pragma unroll
    for (int i = 0; i < 16; i++) {
        int d = i*8 + (lane & 3)*2;
        uint32_t h2, l2;
        packsplit(O[i][0]*inv0, O[i][1]*inv0, h2, l2);
        *(uint32_t*)(aoh + base0 + d) = h2;
        *(uint32_t*)(aol + base0 + d) = l2;
        packsplit(O[i][2]*inv1, O[i][3]*inv1, h2, l2);
        *(uint32_t*)(aoh + base1 + d) = h2;
        *(uint32_t*)(aol + base1 + d) = l2;
    }
}

// ======================= Launch =======================
extern "C" void kernel_launch(void* const* d_in, const int* in_sizes, int n_in,
                              void* d_out, int out_size)
{
    const float* hidden = (const float*)d_in[0];
    const int*   pos    = (const int*)  d_in[1];
    const float* wq     = (const float*)d_in[2];
    const float* bq     = (const float*)d_in[3];
    const float* wk     = (const float*)d_in[4];
    const float* bk     = (const float*)d_in[5];
    const float* wv     = (const float*)d_in[6];
    const float* bv     = (const float*)d_in[7];
    const float* wo     = (const float*)d_in[8];
    float* out = (float*)d_out;

    __nv_bfloat16 *hh, *hl, *qwh, *qwl, *owh, *owl;
    __nv_bfloat16 *qhi, *qlo, *khi, *klo, *vth, *vtl, *aoh, *aol;
    float *qkv, *bias, *ct, *st;
    cudaGetSymbolAddress((void**)&hh,  g_hid_hi);
    cudaGetSymbolAddress((void**)&hl,  g_hid_lo);
    cudaGetSymbolAddress((void**)&qwh, g_wqkv_hi);
    cudaGetSymbolAddress((void**)&qwl, g_wqkv_lo);
    cudaGetSymbolAddress((void**)&owh, g_wo_hi);
    cudaGetSymbolAddress((void**)&owl, g_wo_lo);
    cudaGetSymbolAddress((void**)&qhi, g_q_hi);
    cudaGetSymbolAddress((void**)&qlo, g_q_lo);
    cudaGetSymbolAddress((void**)&khi, g_k_hi);
    cudaGetSymbolAddress((void**)&klo, g_k_lo);
    cudaGetSymbolAddress((void**)&vth, g_vt_hi);
    cudaGetSymbolAddress((void**)&vtl, g_vt_lo);
    cudaGetSymbolAddress((void**)&aoh, g_ao_hi);
    cudaGetSymbolAddress((void**)&aol, g_ao_lo);
    cudaGetSymbolAddress((void**)&qkv, g_qkv);
    cudaGetSymbolAddress((void**)&bias,g_bias);
    cudaGetSymbolAddress((void**)&ct,  g_cos);
    cudaGetSymbolAddress((void**)&st,  g_sin);

    cudaFuncSetAttribute(gemm_mma_kernel, cudaFuncAttributeMaxDynamicSharedMemorySize, GEMM_SMEM);
    cudaFuncSetAttribute(flash_mma_kernel, cudaFuncAttributeMaxDynamicSharedMemorySize, FLASH_SMEM);

    // 1) hidden split
    int n4h = MTOT * DMODEL / 4;
    conv_split_kernel<<<(n4h + 255)/256, 256>>>((const float4*)hidden, (uint2*)hh, (uint2*)hl, n4h);
    // 2) weights (merged)
    conv_weights_kernel<<<dim3(DMODEL/32, 320), dim3(32,8)>>>(wq, wk, wv, wo, qwh, qwl, owh, owl);
    // 3) bias + rope table (merged)
    bias_table_kernel<<<(QKVN + SEQ*64 + 255)/256, 256>>>(bq, bk, bv, bias, ct, st);
    // 4) fused QKV projection
    gemm_mma_kernel<<<dim3(QKVN/GNT, MTOT/GMT), 256, GEMM_SMEM>>>(hh, hl, qwh, qwl, bias, qkv, DMODEL, QKVN);
    // 5) RoPE -> bf16 q/k
    rope_bf16_kernel<<<(MTOT*40*64 + 255)/256, 256>>>(qkv, pos, ct, st, qhi, qlo, khi, klo);
    // 6) V transpose-convert
    vconv_kernel<<<dim3(SEQ/32, HDIM/32, BATCH*NKV), dim3(32,8)>>>(qkv, vth, vtl);
    // 7) flash attention (split-bf16 HMMA)
    flash_mma_kernel<<<dim3(SEQ/FBQ, NH, BATCH), 256, FLASH_SMEM>>>(
        qhi, qlo, khi, klo, vth, vtl, aoh, aol);
    // 8) out projection
    gemm_mma_kernel<<<dim3(DMODEL/GNT, MTOT/GMT), 256, GEMM_SMEM>>>(aoh, aol, owh, owl, nullptr, out, DMODEL, DMODEL);
}